// round 13
// baseline (speedup 1.0000x reference)
#include <cuda_runtime.h>
#include <cstdint>

#define B_SZ   8192
#define EPER   64
#define PPER   16
#define D_SZ   128
#define MN     64
#define MD     128
#define OUTD   256
#define TM     16
#define NTHR   256

// dynamic smem layout (bytes) — R8 layout:
//   [0     .. 9216 )  s_eidx 4096 | s_pidx 1024 | s_mc 4096  (dead after stage3-sync;
//                                                            s_m2 (8192) aliases here)
//   [9216  .. 17408)  s_sem  [TM*D]  8192
//   [17408 .. 25600)  s_h1   [TM*MD] 8192  (dead after stage 3)
//   [17408 .. 33792)  s_part [16*64 float4] 16384  (overlaps dead s_h1)
#define SMEM_BYTES 33792

typedef unsigned long long u64;

__device__ __forceinline__ u64 pack2(float lo, float hi) {
    u64 r; asm("mov.b64 %0, {%1, %2};" : "=l"(r) : "f"(lo), "f"(hi)); return r;
}
__device__ __forceinline__ float2 unpack2(u64 v) {
    float2 r; asm("mov.b64 {%0, %1}, %2;" : "=f"(r.x), "=f"(r.y) : "l"(v)); return r;
}
__device__ __forceinline__ void fma2(u64& d, u64 a, u64 b) {   // d = a*b + d (2 lanes)
    asm("fma.rn.f32x2 %0, %1, %2, %0;" : "+l"(d) : "l"(a), "l"(b));
}
__device__ __forceinline__ void add2(u64& d, u64 a) {          // d = d + a (2 lanes)
    asm("add.rn.f32x2 %0, %0, %1;" : "+l"(d) : "l"(a));
}
__device__ __forceinline__ void mul2(u64& d, u64 a) {          // d = d * a (2 lanes)
    asm("mul.rn.f32x2 %0, %0, %1;" : "+l"(d) : "l"(a));
}

__global__ __launch_bounds__(NTHR, 4)
void subgraph_fused_kernel(const int*   __restrict__ eidx,
                           const int*   __restrict__ pidx,
                           const float* __restrict__ mc,
                           const float* __restrict__ etab,
                           const float* __restrict__ ptab,
                           const float* __restrict__ W1,
                           const float* __restrict__ b1,
                           const float* __restrict__ W2,
                           const float* __restrict__ b2,
                           const float* __restrict__ Wf,
                           const float* __restrict__ bf,
                           float*       __restrict__ out)
{
    extern __shared__ char smem_raw[];
    int*    s_eidx = (int*)smem_raw;                   // TM*EPER
    int*    s_pidx = s_eidx + TM * EPER;               // TM*PPER
    float*  s_mc   = (float*)(s_pidx + TM * PPER);     // TM*MN
    float*  s_sem  = s_mc  + TM * MN;                  // TM*D
    float*  s_h1   = s_sem + TM * D_SZ;                // TM*MD
    float*  s_m2   = (float*)smem_raw;                 // aliases idx/mc region
    float4* s_part = (float4*)s_h1;                    // 16 rows x 64 float4

    const int tid     = threadIdx.x;
    const int rowBase = blockIdx.x * TM;

    // ---- stage 0: cooperative vectorized staging ----
    {
        const int4* ge = (const int4*)(eidx + rowBase * EPER);
        if (tid < TM * EPER / 4) ((int4*)s_eidx)[tid] = ge[tid];
        const int4* gp = (const int4*)(pidx + rowBase * PPER);
        if (tid < TM * PPER / 4) ((int4*)s_pidx)[tid] = gp[tid];
        const float4* gm = (const float4*)(mc + rowBase * MN);
        if (tid < TM * MN / 4) ((float4*)s_mc)[tid] = gm[tid];
    }
    __syncthreads();

    // ---- stage 1: gather + mean pool, f32x2-packed accumulate ----
    // warp w -> rows [2w, 2w+2); lane owns features [4*wlane, 4*wlane+4)
    {
        const int warp  = tid >> 5;
        const int wlane = tid & 31;
        const int r0    = warp * 2;
        const float4* etab4 = (const float4*)etab;
        const float4* ptab4 = (const float4*)ptab;
        const int4* idx0 = (const int4*)(s_eidx + (r0 + 0) * EPER);
        const int4* idx1 = (const int4*)(s_eidx + (r0 + 1) * EPER);

        u64 a0lo = 0, a0hi = 0, a1lo = 0, a1hi = 0;   // (f0,f1),(f2,f3) per row

        #pragma unroll 4
        for (int e4 = 0; e4 < EPER / 4; e4++) {
            const int4 i0 = idx0[e4];
            const int4 i1 = idx1[e4];
            const ulonglong2 v0a = *(const ulonglong2*)(etab4 + (size_t)i0.x * 32 + wlane);
            const ulonglong2 v0b = *(const ulonglong2*)(etab4 + (size_t)i0.y * 32 + wlane);
            const ulonglong2 v0c = *(const ulonglong2*)(etab4 + (size_t)i0.z * 32 + wlane);
            const ulonglong2 v0d = *(const ulonglong2*)(etab4 + (size_t)i0.w * 32 + wlane);
            const ulonglong2 v1a = *(const ulonglong2*)(etab4 + (size_t)i1.x * 32 + wlane);
            const ulonglong2 v1b = *(const ulonglong2*)(etab4 + (size_t)i1.y * 32 + wlane);
            const ulonglong2 v1c = *(const ulonglong2*)(etab4 + (size_t)i1.z * 32 + wlane);
            const ulonglong2 v1d = *(const ulonglong2*)(etab4 + (size_t)i1.w * 32 + wlane);
            add2(a0lo, v0a.x); add2(a0hi, v0a.y);
            add2(a0lo, v0b.x); add2(a0hi, v0b.y);
            add2(a0lo, v0c.x); add2(a0hi, v0c.y);
            add2(a0lo, v0d.x); add2(a0hi, v0d.y);
            add2(a1lo, v1a.x); add2(a1hi, v1a.y);
            add2(a1lo, v1b.x); add2(a1hi, v1b.y);
            add2(a1lo, v1c.x); add2(a1hi, v1c.y);
            add2(a1lo, v1d.x); add2(a1hi, v1d.y);
        }
        const u64 se2 = pack2(0.5f / EPER, 0.5f / EPER);
        mul2(a0lo, se2); mul2(a0hi, se2);
        mul2(a1lo, se2); mul2(a1hi, se2);

        const u64 sp2 = pack2(0.5f / PPER, 0.5f / PPER);
        const int4* pdx0 = (const int4*)(s_pidx + (r0 + 0) * PPER);
        const int4* pdx1 = (const int4*)(s_pidx + (r0 + 1) * PPER);
        #pragma unroll
        for (int e4 = 0; e4 < PPER / 4; e4++) {
            const int4 i0 = pdx0[e4];
            const int4 i1 = pdx1[e4];
            const ulonglong2 v0a = *(const ulonglong2*)(ptab4 + (size_t)i0.x * 32 + wlane);
            const ulonglong2 v0b = *(const ulonglong2*)(ptab4 + (size_t)i0.y * 32 + wlane);
            const ulonglong2 v0c = *(const ulonglong2*)(ptab4 + (size_t)i0.z * 32 + wlane);
            const ulonglong2 v0d = *(const ulonglong2*)(ptab4 + (size_t)i0.w * 32 + wlane);
            const ulonglong2 v1a = *(const ulonglong2*)(ptab4 + (size_t)i1.x * 32 + wlane);
            const ulonglong2 v1b = *(const ulonglong2*)(ptab4 + (size_t)i1.y * 32 + wlane);
            const ulonglong2 v1c = *(const ulonglong2*)(ptab4 + (size_t)i1.z * 32 + wlane);
            const ulonglong2 v1d = *(const ulonglong2*)(ptab4 + (size_t)i1.w * 32 + wlane);
            fma2(a0lo, v0a.x, sp2); fma2(a0hi, v0a.y, sp2);
            fma2(a0lo, v0b.x, sp2); fma2(a0hi, v0b.y, sp2);
            fma2(a0lo, v0c.x, sp2); fma2(a0hi, v0c.y, sp2);
            fma2(a0lo, v0d.x, sp2); fma2(a0hi, v0d.y, sp2);
            fma2(a1lo, v1a.x, sp2); fma2(a1hi, v1a.y, sp2);
            fma2(a1lo, v1b.x, sp2); fma2(a1hi, v1b.y, sp2);
            fma2(a1lo, v1c.x, sp2); fma2(a1hi, v1c.y, sp2);
            fma2(a1lo, v1d.x, sp2); fma2(a1hi, v1d.y, sp2);
        }
        ulonglong2 st0; st0.x = a0lo; st0.y = a0hi;
        ulonglong2 st1; st1.x = a1lo; st1.y = a1hi;
        *(ulonglong2*)(((float4*)(s_sem + (r0 + 0) * D_SZ)) + wlane) = st0;
        *(ulonglong2*)(((float4*)(s_sem + (r0 + 1) * D_SZ)) + wlane) = st1;
    }
    // no barrier: s_sem first read in stage 4 (two barriers later)

    const int lane = tid & (D_SZ - 1);   // 0..127 : feature column
    const int grp  = tid >> 7;           // 0/1

    // ---- stage 2: h1 = relu(mc @ W1 + b1), f32x2 split-accumulator ----
    {
        u64 a2[8];
        const float bb = b1[lane];
        #pragma unroll
        for (int r = 0; r < 8; r++) a2[r] = pack2(bb, 0.f);
        const float4* smc4 = (const float4*)s_mc;
        #pragma unroll 4
        for (int i4 = 0; i4 < MN / 4; i4++) {
            const float w0 = W1[(4 * i4 + 0) * MD + lane];
            const float w1 = W1[(4 * i4 + 1) * MD + lane];
            const float w2 = W1[(4 * i4 + 2) * MD + lane];
            const float w3 = W1[(4 * i4 + 3) * MD + lane];
            const u64 p01 = pack2(w0, w1);
            const u64 p23 = pack2(w2, w3);
            #pragma unroll
            for (int r = 0; r < 8; r++) {
                const ulonglong2 m = *(const ulonglong2*)(smc4 + (grp + 2 * r) * (MN / 4) + i4);
                fma2(a2[r], m.x, p01);
                fma2(a2[r], m.y, p23);
            }
        }
        #pragma unroll
        for (int r = 0; r < 8; r++) {
            const float2 t = unpack2(a2[r]);
            s_h1[(grp + 2 * r) * MD + lane] = fmaxf(t.x + t.y, 0.f);
        }
    }
    __syncthreads();

    // ---- stage 3: m2 = relu(h1 @ W2 + b2), f32x2; m2 aliases idx/mc region ----
    {
        u64 a2[8];
        const float bb = b2[lane];
        #pragma unroll
        for (int r = 0; r < 8; r++) a2[r] = pack2(bb, 0.f);
        const float4* sh14 = (const float4*)s_h1;
        #pragma unroll 4
        for (int i4 = 0; i4 < MD / 4; i4++) {
            const float w0 = W2[(4 * i4 + 0) * MD + lane];
            const float w1 = W2[(4 * i4 + 1) * MD + lane];
            const float w2 = W2[(4 * i4 + 2) * MD + lane];
            const float w3 = W2[(4 * i4 + 3) * MD + lane];
            const u64 p01 = pack2(w0, w1);
            const u64 p23 = pack2(w2, w3);
            #pragma unroll
            for (int r = 0; r < 8; r++) {
                const ulonglong2 h = *(const ulonglong2*)(sh14 + (grp + 2 * r) * (MD / 4) + i4);
                fma2(a2[r], h.x, p01);
                fma2(a2[r], h.y, p23);
            }
        }
        __syncthreads();   // all readers of aliased region and s_h1 done
        #pragma unroll
        for (int r = 0; r < 8; r++) {
            const float2 t = unpack2(a2[r]);
            s_m2[(grp + 2 * r) * MD + lane] = fmaxf(t.x + t.y, 0.f);
        }
    }
    __syncthreads();

    // ---- stage 4: out = relu(concat(sem, m2) @ Wf + bf), k-split + f32x2 ----
    // tx = tid&63 (cols 4tx..4tx+3), ty = (tid>>6)&1 (rows 8ty..8ty+7),
    // tz = tid>>7 (k-half). acc lanes: (even-k partial, odd-k partial).
    {
        const int tx = tid & 63;
        const int ty = (tid >> 6) & 1;
        const int tz = tid >> 7;

        u64 acc2[8][4];
        #pragma unroll
        for (int r = 0; r < 8; r++)
            #pragma unroll
            for (int c = 0; c < 4; c++) acc2[r][c] = 0;

        const float4* act4 = tz ? (const float4*)s_m2 : (const float4*)s_sem;
        const float*  WfH  = Wf + (size_t)(tz * D_SZ) * OUTD;

        #pragma unroll 2
        for (int k4 = 0; k4 < D_SZ / 4; k4++) {
            const float4 w0 = ((const float4*)(WfH + (size_t)(4 * k4 + 0) * OUTD))[tx];
            const float4 w1 = ((const float4*)(WfH + (size_t)(4 * k4 + 1) * OUTD))[tx];
            const float4 w2 = ((const float4*)(WfH + (size_t)(4 * k4 + 2) * OUTD))[tx];
            const float4 w3 = ((const float4*)(WfH + (size_t)(4 * k4 + 3) * OUTD))[tx];
            u64 p01[4], p23[4];
            p01[0] = pack2(w0.x, w1.x); p01[1] = pack2(w0.y, w1.y);
            p01[2] = pack2(w0.z, w1.z); p01[3] = pack2(w0.w, w1.w);
            p23[0] = pack2(w2.x, w3.x); p23[1] = pack2(w2.y, w3.y);
            p23[2] = pack2(w2.z, w3.z); p23[3] = pack2(w2.w, w3.w);
            #pragma unroll
            for (int r = 0; r < 8; r++) {
                const ulonglong2 av =
                    *(const ulonglong2*)(act4 + (8 * ty + r) * (D_SZ / 4) + k4);
                fma2(acc2[r][0], av.x, p01[0]);
                fma2(acc2[r][1], av.x, p01[1]);
                fma2(acc2[r][2], av.x, p01[2]);
                fma2(acc2[r][3], av.x, p01[3]);
                fma2(acc2[r][0], av.y, p23[0]);
                fma2(acc2[r][1], av.y, p23[1]);
                fma2(acc2[r][2], av.y, p23[2]);
                fma2(acc2[r][3], av.y, p23[3]);
            }
        }

        // horizontal add; tz=1 publishes partials (overlapping dead s_h1)
        if (tz) {
            #pragma unroll
            for (int r = 0; r < 8; r++) {
                float4 p;
                { const float2 t = unpack2(acc2[r][0]); p.x = t.x + t.y; }
                { const float2 t = unpack2(acc2[r][1]); p.y = t.x + t.y; }
                { const float2 t = unpack2(acc2[r][2]); p.z = t.x + t.y; }
                { const float2 t = unpack2(acc2[r][3]); p.w = t.x + t.y; }
                s_part[(8 * ty + r) * 64 + tx] = p;
            }
        }
        __syncthreads();

        if (!tz) {
            const float4 bfv = ((const float4*)bf)[tx];
            #pragma unroll
            for (int r = 0; r < 8; r++) {
                const float4 p = s_part[(8 * ty + r) * 64 + tx];
                float4 o;
                { const float2 t = unpack2(acc2[r][0]); o.x = fmaxf(t.x + t.y + p.x + bfv.x, 0.f); }
                { const float2 t = unpack2(acc2[r][1]); o.y = fmaxf(t.x + t.y + p.y + bfv.y, 0.f); }
                { const float2 t = unpack2(acc2[r][2]); o.z = fmaxf(t.x + t.y + p.z + bfv.z, 0.f); }
                { const float2 t = unpack2(acc2[r][3]); o.w = fmaxf(t.x + t.y + p.w + bfv.w, 0.f); }
                ((float4*)(out + (size_t)(rowBase + 8 * ty + r) * OUTD))[tx] = o;
            }
        }
    }
}

extern "C" void kernel_launch(void* const* d_in, const int* in_sizes, int n_in,
                              void* d_out, int out_size)
{
    const int*   eidx = (const int*)d_in[0];
    const int*   pidx = (const int*)d_in[1];
    const float* mc   = (const float*)d_in[2];
    const float* etab = (const float*)d_in[3];
    const float* ptab = (const float*)d_in[4];
    const float* W1   = (const float*)d_in[5];
    const float* b1   = (const float*)d_in[6];
    const float* W2   = (const float*)d_in[7];
    const float* b2   = (const float*)d_in[8];
    const float* Wf   = (const float*)d_in[9];
    const float* bf   = (const float*)d_in[10];
    float* out = (float*)d_out;

    cudaFuncSetAttribute(subgraph_fused_kernel,
                         cudaFuncAttributeMaxDynamicSharedMemorySize, SMEM_BYTES);

    subgraph_fused_kernel<<<B_SZ / TM, NTHR, SMEM_BYTES>>>(
        eidx, pidx, mc, etab, ptab, W1, b1, W2, b2, Wf, bf, out);
}

// round 14
// speedup vs baseline: 1.4276x; 1.4276x over previous
#include <cuda_runtime.h>

#define B_SZ   8192
#define EPER   64
#define PPER   16
#define D_SZ   128
#define MN     64
#define MD     128
#define OUTD   256
#define TM     16
#define NTHR   256

// dynamic smem layout (bytes) — R8 layout:
//   [0     .. 9216 )  s_eidx 4096 | s_pidx 1024 | s_mc 4096  (dead after stage3-sync;
//                                                            s_m2 (8192) aliases here)
//   [9216  .. 17408)  s_sem  [TM*D]  8192
//   [17408 .. 25600)  s_h1   [TM*MD] 8192  (dead after stage 3)
//   [17408 .. 33792)  s_part [16*64 float4] 16384  (overlaps dead s_h1)
#define SMEM_BYTES 33792

__global__ __launch_bounds__(NTHR, 5)
void subgraph_fused_kernel(const int*   __restrict__ eidx,
                           const int*   __restrict__ pidx,
                           const float* __restrict__ mc,
                           const float* __restrict__ etab,
                           const float* __restrict__ ptab,
                           const float* __restrict__ W1,
                           const float* __restrict__ b1,
                           const float* __restrict__ W2,
                           const float* __restrict__ b2,
                           const float* __restrict__ Wf,
                           const float* __restrict__ bf,
                           float*       __restrict__ out)
{
    extern __shared__ char smem_raw[];
    int*    s_eidx = (int*)smem_raw;                   // TM*EPER
    int*    s_pidx = s_eidx + TM * EPER;               // TM*PPER
    float*  s_mc   = (float*)(s_pidx + TM * PPER);     // TM*MN
    float*  s_sem  = s_mc  + TM * MN;                  // TM*D
    float*  s_h1   = s_sem + TM * D_SZ;                // TM*MD
    float*  s_m2   = (float*)smem_raw;                 // aliases idx/mc region
    float4* s_part = (float4*)s_h1;                    // 16 rows x 64 float4

    const int tid     = threadIdx.x;
    const int rowBase = blockIdx.x * TM;

    // ---- stage 0: cooperative vectorized staging ----
    {
        const int4* ge = (const int4*)(eidx + rowBase * EPER);   // 256 int4
        if (tid < TM * EPER / 4) ((int4*)s_eidx)[tid] = ge[tid];
        const int4* gp = (const int4*)(pidx + rowBase * PPER);   // 64 int4
        if (tid < TM * PPER / 4) ((int4*)s_pidx)[tid] = gp[tid];
        const float4* gm = (const float4*)(mc + rowBase * MN);   // 256 float4
        if (tid < TM * MN / 4) ((float4*)s_mc)[tid] = gm[tid];
    }
    __syncthreads();

    // ---- stage 1: gather + mean pool ----
    // warp w -> rows [2w, 2w+2); lane owns features [4*wlane, 4*wlane+4)
    {
        const int warp  = tid >> 5;
        const int wlane = tid & 31;
        const int r0    = warp * 2;
        const float4* etab4 = (const float4*)etab;
        const float4* ptab4 = (const float4*)ptab;
        const int4* idx0 = (const int4*)(s_eidx + (r0 + 0) * EPER);
        const int4* idx1 = (const int4*)(s_eidx + (r0 + 1) * EPER);
        const float se = 0.5f / EPER, sp = 0.5f / PPER;

        float4 acc0 = make_float4(0.f, 0.f, 0.f, 0.f);
        float4 acc1 = make_float4(0.f, 0.f, 0.f, 0.f);

        #pragma unroll 4
        for (int e4 = 0; e4 < EPER / 4; e4++) {
            const int4 i0 = idx0[e4];
            const int4 i1 = idx1[e4];
            const float4 v0a = etab4[(size_t)i0.x * 32 + wlane];
            const float4 v0b = etab4[(size_t)i0.y * 32 + wlane];
            const float4 v0c = etab4[(size_t)i0.z * 32 + wlane];
            const float4 v0d = etab4[(size_t)i0.w * 32 + wlane];
            const float4 v1a = etab4[(size_t)i1.x * 32 + wlane];
            const float4 v1b = etab4[(size_t)i1.y * 32 + wlane];
            const float4 v1c = etab4[(size_t)i1.z * 32 + wlane];
            const float4 v1d = etab4[(size_t)i1.w * 32 + wlane];
            acc0.x += (v0a.x + v0b.x) + (v0c.x + v0d.x);
            acc0.y += (v0a.y + v0b.y) + (v0c.y + v0d.y);
            acc0.z += (v0a.z + v0b.z) + (v0c.z + v0d.z);
            acc0.w += (v0a.w + v0b.w) + (v0c.w + v0d.w);
            acc1.x += (v1a.x + v1b.x) + (v1c.x + v1d.x);
            acc1.y += (v1a.y + v1b.y) + (v1c.y + v1d.y);
            acc1.z += (v1a.z + v1b.z) + (v1c.z + v1d.z);
            acc1.w += (v1a.w + v1b.w) + (v1c.w + v1d.w);
        }
        acc0.x *= se; acc0.y *= se; acc0.z *= se; acc0.w *= se;
        acc1.x *= se; acc1.y *= se; acc1.z *= se; acc1.w *= se;

        const int4* pdx0 = (const int4*)(s_pidx + (r0 + 0) * PPER);
        const int4* pdx1 = (const int4*)(s_pidx + (r0 + 1) * PPER);
        #pragma unroll
        for (int e4 = 0; e4 < PPER / 4; e4++) {
            const int4 i0 = pdx0[e4];
            const int4 i1 = pdx1[e4];
            const float4 v0a = ptab4[(size_t)i0.x * 32 + wlane];
            const float4 v0b = ptab4[(size_t)i0.y * 32 + wlane];
            const float4 v0c = ptab4[(size_t)i0.z * 32 + wlane];
            const float4 v0d = ptab4[(size_t)i0.w * 32 + wlane];
            const float4 v1a = ptab4[(size_t)i1.x * 32 + wlane];
            const float4 v1b = ptab4[(size_t)i1.y * 32 + wlane];
            const float4 v1c = ptab4[(size_t)i1.z * 32 + wlane];
            const float4 v1d = ptab4[(size_t)i1.w * 32 + wlane];
            acc0.x = fmaf((v0a.x + v0b.x) + (v0c.x + v0d.x), sp, acc0.x);
            acc0.y = fmaf((v0a.y + v0b.y) + (v0c.y + v0d.y), sp, acc0.y);
            acc0.z = fmaf((v0a.z + v0b.z) + (v0c.z + v0d.z), sp, acc0.z);
            acc0.w = fmaf((v0a.w + v0b.w) + (v0c.w + v0d.w), sp, acc0.w);
            acc1.x = fmaf((v1a.x + v1b.x) + (v1c.x + v1d.x), sp, acc1.x);
            acc1.y = fmaf((v1a.y + v1b.y) + (v1c.y + v1d.y), sp, acc1.y);
            acc1.z = fmaf((v1a.z + v1b.z) + (v1c.z + v1d.z), sp, acc1.z);
            acc1.w = fmaf((v1a.w + v1b.w) + (v1c.w + v1d.w), sp, acc1.w);
        }
        ((float4*)(s_sem + (r0 + 0) * D_SZ))[wlane] = acc0;
        ((float4*)(s_sem + (r0 + 1) * D_SZ))[wlane] = acc1;
    }
    // no barrier: s_sem first read in stage 4 (two barriers later)

    const int lane = tid & (D_SZ - 1);   // 0..127 : feature column
    const int grp  = tid >> 7;           // 0/1

    // ---- stage 2: h1 = relu(mc @ W1 + b1) ----
    {
        float a[8];
        const float bb = b1[lane];
        #pragma unroll
        for (int r = 0; r < 8; r++) a[r] = bb;
        const float4* smc4 = (const float4*)s_mc;
        #pragma unroll 4
        for (int i4 = 0; i4 < MN / 4; i4++) {
            const float w0 = W1[(4 * i4 + 0) * MD + lane];
            const float w1 = W1[(4 * i4 + 1) * MD + lane];
            const float w2 = W1[(4 * i4 + 2) * MD + lane];
            const float w3 = W1[(4 * i4 + 3) * MD + lane];
            #pragma unroll
            for (int r = 0; r < 8; r++) {
                const float4 m = smc4[(grp + 2 * r) * (MN / 4) + i4];
                float t = fmaf(m.x, w0, a[r]);
                t = fmaf(m.y, w1, t);
                t = fmaf(m.z, w2, t);
                a[r] = fmaf(m.w, w3, t);
            }
        }
        #pragma unroll
        for (int r = 0; r < 8; r++)
            s_h1[(grp + 2 * r) * MD + lane] = fmaxf(a[r], 0.f);
    }
    __syncthreads();

    // ---- stage 3: m2 = relu(h1 @ W2 + b2); m2 aliases idx/mc region ----
    {
        float a[8];
        const float bb = b2[lane];
        #pragma unroll
        for (int r = 0; r < 8; r++) a[r] = bb;
        const float4* sh14 = (const float4*)s_h1;
        #pragma unroll 4
        for (int i4 = 0; i4 < MD / 4; i4++) {
            const float w0 = W2[(4 * i4 + 0) * MD + lane];
            const float w1 = W2[(4 * i4 + 1) * MD + lane];
            const float w2 = W2[(4 * i4 + 2) * MD + lane];
            const float w3 = W2[(4 * i4 + 3) * MD + lane];
            #pragma unroll
            for (int r = 0; r < 8; r++) {
                const float4 h = sh14[(grp + 2 * r) * (MD / 4) + i4];
                float t = fmaf(h.x, w0, a[r]);
                t = fmaf(h.y, w1, t);
                t = fmaf(h.z, w2, t);
                a[r] = fmaf(h.w, w3, t);
            }
        }
        __syncthreads();   // all readers of aliased region and s_h1 done
        #pragma unroll
        for (int r = 0; r < 8; r++)
            s_m2[(grp + 2 * r) * MD + lane] = fmaxf(a[r], 0.f);
    }
    __syncthreads();

    // ---- stage 4: out = relu(concat(sem, m2) @ Wf + bf), k-split ----
    // tx = tid&63 (cols 4tx..4tx+3), ty = (tid>>6)&1 (rows 8ty..8ty+7),
    // tz = tid>>7 (k-half). 2 Wf rows per step (lower live-reg peak for occ=5).
    {
        const int tx = tid & 63;
        const int ty = (tid >> 6) & 1;
        const int tz = tid >> 7;

        float acc[8][4];
        #pragma unroll
        for (int r = 0; r < 8; r++)
            #pragma unroll
            for (int c = 0; c < 4; c++) acc[r][c] = 0.f;

        const float2* act2 = tz ? (const float2*)s_m2 : (const float2*)s_sem;
        const float*  WfH  = Wf + (size_t)(tz * D_SZ) * OUTD;

        #pragma unroll 4
        for (int k2 = 0; k2 < D_SZ / 2; k2++) {
            const float4 w0 = ((const float4*)(WfH + (size_t)(2 * k2 + 0) * OUTD))[tx];
            const float4 w1 = ((const float4*)(WfH + (size_t)(2 * k2 + 1) * OUTD))[tx];
            #pragma unroll
            for (int r = 0; r < 8; r++) {
                const float2 a = act2[(8 * ty + r) * (D_SZ / 2) + k2];
                acc[r][0] = fmaf(a.x, w0.x, acc[r][0]);
                acc[r][1] = fmaf(a.x, w0.y, acc[r][1]);
                acc[r][2] = fmaf(a.x, w0.z, acc[r][2]);
                acc[r][3] = fmaf(a.x, w0.w, acc[r][3]);
                acc[r][0] = fmaf(a.y, w1.x, acc[r][0]);
                acc[r][1] = fmaf(a.y, w1.y, acc[r][1]);
                acc[r][2] = fmaf(a.y, w1.z, acc[r][2]);
                acc[r][3] = fmaf(a.y, w1.w, acc[r][3]);
            }
        }

        // tz=1 publishes partials (overlapping dead s_h1 region)
        if (tz) {
            #pragma unroll
            for (int r = 0; r < 8; r++)
                s_part[(8 * ty + r) * 64 + tx] =
                    make_float4(acc[r][0], acc[r][1], acc[r][2], acc[r][3]);
        }
        __syncthreads();

        if (!tz) {
            const float4 bfv = ((const float4*)bf)[tx];
            #pragma unroll
            for (int r = 0; r < 8; r++) {
                const float4 p = s_part[(8 * ty + r) * 64 + tx];
                float4 o;
                o.x = fmaxf(acc[r][0] + p.x + bfv.x, 0.f);
                o.y = fmaxf(acc[r][1] + p.y + bfv.y, 0.f);
                o.z = fmaxf(acc[r][2] + p.z + bfv.z, 0.f);
                o.w = fmaxf(acc[r][3] + p.w + bfv.w, 0.f);
                ((float4*)(out + (size_t)(rowBase + 8 * ty + r) * OUTD))[tx] = o;
            }
        }
    }
}

extern "C" void kernel_launch(void* const* d_in, const int* in_sizes, int n_in,
                              void* d_out, int out_size)
{
    const int*   eidx = (const int*)d_in[0];
    const int*   pidx = (const int*)d_in[1];
    const float* mc   = (const float*)d_in[2];
    const float* etab = (const float*)d_in[3];
    const float* ptab = (const float*)d_in[4];
    const float* W1   = (const float*)d_in[5];
    const float* b1   = (const float*)d_in[6];
    const float* W2   = (const float*)d_in[7];
    const float* b2   = (const float*)d_in[8];
    const float* Wf   = (const float*)d_in[9];
    const float* bf   = (const float*)d_in[10];
    float* out = (float*)d_out;

    cudaFuncSetAttribute(subgraph_fused_kernel,
                         cudaFuncAttributeMaxDynamicSharedMemorySize, SMEM_BYTES);

    subgraph_fused_kernel<<<B_SZ / TM, NTHR, SMEM_BYTES>>>(
        eidx, pidx, mc, etab, ptab, W1, b1, W2, b2, Wf, bf, out);
}

// round 15
// speedup vs baseline: 4.6599x; 3.2642x over previous
#include <cuda_runtime.h>

#define B_SZ   8192
#define EPER   64
#define PPER   16
#define D_SZ   128
#define MN     64
#define MD     128
#define OUTD   256
#define TM     16
#define NTHR   256

// dynamic smem layout (bytes) — R8 layout:
//   [0     .. 9216 )  s_eidx 4096 | s_pidx 1024 | s_mc 4096  (dead after stage3-sync;
//                                                            s_m2 (8192) aliases here)
//   [9216  .. 17408)  s_sem  [TM*D]  8192
//   [17408 .. 25600)  s_h1   [TM*MD] 8192  (dead after stage 3)
//   [17408 .. 33792)  s_part [16*128 float2] 16384  (overlaps dead s_h1)
#define SMEM_BYTES 33792

__global__ __launch_bounds__(NTHR, 4)
void subgraph_fused_kernel(const int*   __restrict__ eidx,
                           const int*   __restrict__ pidx,
                           const float* __restrict__ mc,
                           const float* __restrict__ etab,
                           const float* __restrict__ ptab,
                           const float* __restrict__ W1,
                           const float* __restrict__ b1,
                           const float* __restrict__ W2,
                           const float* __restrict__ b2,
                           const float* __restrict__ Wf,
                           const float* __restrict__ bf,
                           float*       __restrict__ out)
{
    extern __shared__ char smem_raw[];
    int*    s_eidx = (int*)smem_raw;                   // TM*EPER
    int*    s_pidx = s_eidx + TM * EPER;               // TM*PPER
    float*  s_mc   = (float*)(s_pidx + TM * PPER);     // TM*MN
    float*  s_sem  = s_mc  + TM * MN;                  // TM*D
    float*  s_h1   = s_sem + TM * D_SZ;                // TM*MD
    float*  s_m2   = (float*)smem_raw;                 // aliases idx/mc region
    float2* s_part = (float2*)s_h1;                    // 16 rows x 128 float2 (16 KB)

    const int tid     = threadIdx.x;
    const int rowBase = blockIdx.x * TM;

    // ---- stage 0: cooperative vectorized staging ----
    {
        const int4* ge = (const int4*)(eidx + rowBase * EPER);   // 256 int4
        if (tid < TM * EPER / 4) ((int4*)s_eidx)[tid] = ge[tid];
        const int4* gp = (const int4*)(pidx + rowBase * PPER);   // 64 int4
        if (tid < TM * PPER / 4) ((int4*)s_pidx)[tid] = gp[tid];
        const float4* gm = (const float4*)(mc + rowBase * MN);   // 256 float4
        if (tid < TM * MN / 4) ((float4*)s_mc)[tid] = gm[tid];
    }
    __syncthreads();

    // ---- stage 1: gather + mean pool (R8, unchanged) ----
    {
        const int warp  = tid >> 5;
        const int wlane = tid & 31;
        const int r0    = warp * 2;
        const float4* etab4 = (const float4*)etab;
        const float4* ptab4 = (const float4*)ptab;
        const int4* idx0 = (const int4*)(s_eidx + (r0 + 0) * EPER);
        const int4* idx1 = (const int4*)(s_eidx + (r0 + 1) * EPER);
        const float se = 0.5f / EPER, sp = 0.5f / PPER;

        float4 acc0 = make_float4(0.f, 0.f, 0.f, 0.f);
        float4 acc1 = make_float4(0.f, 0.f, 0.f, 0.f);

        #pragma unroll 4
        for (int e4 = 0; e4 < EPER / 4; e4++) {
            const int4 i0 = idx0[e4];
            const int4 i1 = idx1[e4];
            const float4 v0a = etab4[(size_t)i0.x * 32 + wlane];
            const float4 v0b = etab4[(size_t)i0.y * 32 + wlane];
            const float4 v0c = etab4[(size_t)i0.z * 32 + wlane];
            const float4 v0d = etab4[(size_t)i0.w * 32 + wlane];
            const float4 v1a = etab4[(size_t)i1.x * 32 + wlane];
            const float4 v1b = etab4[(size_t)i1.y * 32 + wlane];
            const float4 v1c = etab4[(size_t)i1.z * 32 + wlane];
            const float4 v1d = etab4[(size_t)i1.w * 32 + wlane];
            acc0.x += (v0a.x + v0b.x) + (v0c.x + v0d.x);
            acc0.y += (v0a.y + v0b.y) + (v0c.y + v0d.y);
            acc0.z += (v0a.z + v0b.z) + (v0c.z + v0d.z);
            acc0.w += (v0a.w + v0b.w) + (v0c.w + v0d.w);
            acc1.x += (v1a.x + v1b.x) + (v1c.x + v1d.x);
            acc1.y += (v1a.y + v1b.y) + (v1c.y + v1d.y);
            acc1.z += (v1a.z + v1b.z) + (v1c.z + v1d.z);
            acc1.w += (v1a.w + v1b.w) + (v1c.w + v1d.w);
        }
        acc0.x *= se; acc0.y *= se; acc0.z *= se; acc0.w *= se;
        acc1.x *= se; acc1.y *= se; acc1.z *= se; acc1.w *= se;

        const int4* pdx0 = (const int4*)(s_pidx + (r0 + 0) * PPER);
        const int4* pdx1 = (const int4*)(s_pidx + (r0 + 1) * PPER);
        #pragma unroll
        for (int e4 = 0; e4 < PPER / 4; e4++) {
            const int4 i0 = pdx0[e4];
            const int4 i1 = pdx1[e4];
            const float4 v0a = ptab4[(size_t)i0.x * 32 + wlane];
            const float4 v0b = ptab4[(size_t)i0.y * 32 + wlane];
            const float4 v0c = ptab4[(size_t)i0.z * 32 + wlane];
            const float4 v0d = ptab4[(size_t)i0.w * 32 + wlane];
            const float4 v1a = ptab4[(size_t)i1.x * 32 + wlane];
            const float4 v1b = ptab4[(size_t)i1.y * 32 + wlane];
            const float4 v1c = ptab4[(size_t)i1.z * 32 + wlane];
            const float4 v1d = ptab4[(size_t)i1.w * 32 + wlane];
            acc0.x = fmaf((v0a.x + v0b.x) + (v0c.x + v0d.x), sp, acc0.x);
            acc0.y = fmaf((v0a.y + v0b.y) + (v0c.y + v0d.y), sp, acc0.y);
            acc0.z = fmaf((v0a.z + v0b.z) + (v0c.z + v0d.z), sp, acc0.z);
            acc0.w = fmaf((v0a.w + v0b.w) + (v0c.w + v0d.w), sp, acc0.w);
            acc1.x = fmaf((v1a.x + v1b.x) + (v1c.x + v1d.x), sp, acc1.x);
            acc1.y = fmaf((v1a.y + v1b.y) + (v1c.y + v1d.y), sp, acc1.y);
            acc1.z = fmaf((v1a.z + v1b.z) + (v1c.z + v1d.z), sp, acc1.z);
            acc1.w = fmaf((v1a.w + v1b.w) + (v1c.w + v1d.w), sp, acc1.w);
        }
        ((float4*)(s_sem + (r0 + 0) * D_SZ))[wlane] = acc0;
        ((float4*)(s_sem + (r0 + 1) * D_SZ))[wlane] = acc1;
    }
    // no barrier: s_sem first read in stage 4 (two barriers later)

    const int lane = tid & (D_SZ - 1);   // 0..127 : feature column
    const int grp  = tid >> 7;           // 0/1

    // ---- stage 2: h1 = relu(mc @ W1 + b1) (R8, unchanged) ----
    {
        float a[8];
        const float bb = b1[lane];
        #pragma unroll
        for (int r = 0; r < 8; r++) a[r] = bb;
        const float4* smc4 = (const float4*)s_mc;
        #pragma unroll 4
        for (int i4 = 0; i4 < MN / 4; i4++) {
            const float w0 = W1[(4 * i4 + 0) * MD + lane];
            const float w1 = W1[(4 * i4 + 1) * MD + lane];
            const float w2 = W1[(4 * i4 + 2) * MD + lane];
            const float w3 = W1[(4 * i4 + 3) * MD + lane];
            #pragma unroll
            for (int r = 0; r < 8; r++) {
                const float4 m = smc4[(grp + 2 * r) * (MN / 4) + i4];
                float t = fmaf(m.x, w0, a[r]);
                t = fmaf(m.y, w1, t);
                t = fmaf(m.z, w2, t);
                a[r] = fmaf(m.w, w3, t);
            }
        }
        #pragma unroll
        for (int r = 0; r < 8; r++)
            s_h1[(grp + 2 * r) * MD + lane] = fmaxf(a[r], 0.f);
    }
    __syncthreads();

    // ---- stage 3: m2 = relu(h1 @ W2 + b2); m2 aliases idx/mc (R8, unchanged) ----
    {
        float a[8];
        const float bb = b2[lane];
        #pragma unroll
        for (int r = 0; r < 8; r++) a[r] = bb;
        const float4* sh14 = (const float4*)s_h1;
        #pragma unroll 4
        for (int i4 = 0; i4 < MD / 4; i4++) {
            const float w0 = W2[(4 * i4 + 0) * MD + lane];
            const float w1 = W2[(4 * i4 + 1) * MD + lane];
            const float w2 = W2[(4 * i4 + 2) * MD + lane];
            const float w3 = W2[(4 * i4 + 3) * MD + lane];
            #pragma unroll
            for (int r = 0; r < 8; r++) {
                const float4 h = sh14[(grp + 2 * r) * (MD / 4) + i4];
                float t = fmaf(h.x, w0, a[r]);
                t = fmaf(h.y, w1, t);
                t = fmaf(h.z, w2, t);
                a[r] = fmaf(h.w, w3, t);
            }
        }
        __syncthreads();   // all readers of aliased region and s_h1 done
        #pragma unroll
        for (int r = 0; r < 8; r++)
            s_m2[(grp + 2 * r) * MD + lane] = fmaxf(a[r], 0.f);
    }
    __syncthreads();

    // ---- stage 4: out = relu(concat(sem, m2) @ Wf + bf) ----
    // NEW mapping: tx = tid&127 owns cols (2tx, 2tx+1) for ALL 16 rows;
    // tz = tid>>7 is the k-half. Each Wf element read by exactly ONE thread
    // per CTA (halves Wf L2 traffic vs R8). Activation reads = LDS.128
    // broadcasts (all lanes same address).
    {
        const int tx = tid & 127;
        const int tz = tid >> 7;

        float acc[16][2];
        #pragma unroll
        for (int r = 0; r < 16; r++) { acc[r][0] = 0.f; acc[r][1] = 0.f; }

        const float4* act4 = tz ? (const float4*)s_m2 : (const float4*)s_sem;
        const float*  WfH  = Wf + (size_t)(tz * D_SZ) * OUTD;

        #pragma unroll 2
        for (int k4 = 0; k4 < D_SZ / 4; k4++) {
            const float2 w0 = ((const float2*)(WfH + (size_t)(4 * k4 + 0) * OUTD))[tx];
            const float2 w1 = ((const float2*)(WfH + (size_t)(4 * k4 + 1) * OUTD))[tx];
            const float2 w2 = ((const float2*)(WfH + (size_t)(4 * k4 + 2) * OUTD))[tx];
            const float2 w3 = ((const float2*)(WfH + (size_t)(4 * k4 + 3) * OUTD))[tx];
            #pragma unroll
            for (int r = 0; r < 16; r++) {
                const float4 a = act4[r * (D_SZ / 4) + k4];
                float t0 = fmaf(a.x, w0.x, acc[r][0]);
                float t1 = fmaf(a.x, w0.y, acc[r][1]);
                t0 = fmaf(a.y, w1.x, t0);
                t1 = fmaf(a.y, w1.y, t1);
                t0 = fmaf(a.z, w2.x, t0);
                t1 = fmaf(a.z, w2.y, t1);
                acc[r][0] = fmaf(a.w, w3.x, t0);
                acc[r][1] = fmaf(a.w, w3.y, t1);
            }
        }

        // tz=1 publishes partials (overlapping dead s_h1 region)
        if (tz) {
            #pragma unroll
            for (int r = 0; r < 16; r++)
                s_part[r * 128 + tx] = make_float2(acc[r][0], acc[r][1]);
        }
        __syncthreads();

        if (!tz) {
            const float2 bfv = ((const float2*)bf)[tx];
            #pragma unroll
            for (int r = 0; r < 16; r++) {
                const float2 p = s_part[r * 128 + tx];
                float2 o;
                o.x = fmaxf(acc[r][0] + p.x + bfv.x, 0.f);
                o.y = fmaxf(acc[r][1] + p.y + bfv.y, 0.f);
                ((float2*)(out + (size_t)(rowBase + r) * OUTD))[tx] = o;
            }
        }
    }
}

extern "C" void kernel_launch(void* const* d_in, const int* in_sizes, int n_in,
                              void* d_out, int out_size)
{
    const int*   eidx = (const int*)d_in[0];
    const int*   pidx = (const int*)d_in[1];
    const float* mc   = (const float*)d_in[2];
    const float* etab = (const float*)d_in[3];
    const float* ptab = (const float*)d_in[4];
    const float* W1   = (const float*)d_in[5];
    const float* b1   = (const float*)d_in[6];
    const float* W2   = (const float*)d_in[7];
    const float* b2   = (const float*)d_in[8];
    const float* Wf   = (const float*)d_in[9];
    const float* bf   = (const float*)d_in[10];
    float* out = (float*)d_out;

    cudaFuncSetAttribute(subgraph_fused_kernel,
                         cudaFuncAttributeMaxDynamicSharedMemorySize, SMEM_BYTES);

    subgraph_fused_kernel<<<B_SZ / TM, NTHR, SMEM_BYTES>>>(
        eidx, pidx, mc, etab, ptab, W1, b1, W2, b2, Wf, bf, out);
}

// round 16
// speedup vs baseline: 4.8099x; 1.0322x over previous
#include <cuda_runtime.h>

#define B_SZ   8192
#define EPER   64
#define PPER   16
#define D_SZ   128
#define MN     64
#define MD     128
#define OUTD   256
#define TM     16
#define NTHR   256

// dynamic smem layout (bytes) — R8 layout:
//   [0     .. 9216 )  s_eidx 4096 | s_pidx 1024 | s_mc 4096  (dead after stage3-sync;
//                                                            s_m2 (8192) aliases here)
//   [9216  .. 17408)  s_sem  [TM*D]  8192
//   [17408 .. 25600)  s_h1   [TM*MD] 8192  (dead after stage 3)
//   [17408 .. 33792)  s_part [16*64 float4] 16384  (overlaps dead s_h1)
#define SMEM_BYTES 33792

__global__ __launch_bounds__(NTHR, 4)
void subgraph_fused_kernel(const int*   __restrict__ eidx,
                           const int*   __restrict__ pidx,
                           const float* __restrict__ mc,
                           const float* __restrict__ etab,
                           const float* __restrict__ ptab,
                           const float* __restrict__ W1,
                           const float* __restrict__ b1,
                           const float* __restrict__ W2,
                           const float* __restrict__ b2,
                           const float* __restrict__ Wf,
                           const float* __restrict__ bf,
                           float*       __restrict__ out)
{
    extern __shared__ char smem_raw[];
    int*    s_eidx = (int*)smem_raw;                   // TM*EPER
    int*    s_pidx = s_eidx + TM * EPER;               // TM*PPER
    float*  s_mc   = (float*)(s_pidx + TM * PPER);     // TM*MN
    float*  s_sem  = s_mc  + TM * MN;                  // TM*D
    float*  s_h1   = s_sem + TM * D_SZ;                // TM*MD
    float*  s_m2   = (float*)smem_raw;                 // aliases idx/mc region
    float4* s_part = (float4*)s_h1;                    // 16 rows x 64 float4

    const int tid     = threadIdx.x;
    const int rowBase = blockIdx.x * TM;

    // ---- stage 0: cooperative vectorized staging ----
    {
        const int4* ge = (const int4*)(eidx + rowBase * EPER);   // 256 int4
        if (tid < TM * EPER / 4) ((int4*)s_eidx)[tid] = ge[tid];
        const int4* gp = (const int4*)(pidx + rowBase * PPER);   // 64 int4
        if (tid < TM * PPER / 4) ((int4*)s_pidx)[tid] = gp[tid];
        const float4* gm = (const float4*)(mc + rowBase * MN);   // 256 float4
        if (tid < TM * MN / 4) ((float4*)s_mc)[tid] = gm[tid];
    }
    __syncthreads();

    const int lane = tid & (D_SZ - 1);   // 0..127 : feature column (stage 2/3 role)
    const int grp  = tid >> 7;           // 0/1

    // ---- stage 1+2 FUSED: entity gather interleaved with motif MLP layer 1 ----
    // Gather role: warp w -> rows [2w, 2w+2); lane owns features [4*wlane,+4).
    // Each of 16 iterations: issue 8 gather LDG.128, then one stage-2 k-slice
    // (independent FMA work that fills the loads' latency shadow), then
    // consume the landed gather values.
    float4 g_acc0, g_acc1;        // gather accumulators
    float  m_a[8];                // stage-2 accumulators
    {
        const int warp  = tid >> 5;
        const int wlane = tid & 31;
        const int r0    = warp * 2;
        const float4* etab4 = (const float4*)etab;
        const int4* idx0 = (const int4*)(s_eidx + (r0 + 0) * EPER);
        const int4* idx1 = (const int4*)(s_eidx + (r0 + 1) * EPER);
        const float4* smc4 = (const float4*)s_mc;

        g_acc0 = make_float4(0.f, 0.f, 0.f, 0.f);
        g_acc1 = make_float4(0.f, 0.f, 0.f, 0.f);
        const float bb = b1[lane];
        #pragma unroll
        for (int r = 0; r < 8; r++) m_a[r] = bb;

        #pragma unroll 4
        for (int it = 0; it < 16; it++) {
            // (a) issue 8 independent gather loads
            const int4 i0 = idx0[it];
            const int4 i1 = idx1[it];
            const float4 v0a = etab4[(size_t)i0.x * 32 + wlane];
            const float4 v0b = etab4[(size_t)i0.y * 32 + wlane];
            const float4 v0c = etab4[(size_t)i0.z * 32 + wlane];
            const float4 v0d = etab4[(size_t)i0.w * 32 + wlane];
            const float4 v1a = etab4[(size_t)i1.x * 32 + wlane];
            const float4 v1b = etab4[(size_t)i1.y * 32 + wlane];
            const float4 v1c = etab4[(size_t)i1.z * 32 + wlane];
            const float4 v1d = etab4[(size_t)i1.w * 32 + wlane];

            // (b) stage-2 slice it (independent of the in-flight loads)
            {
                const float w0 = W1[(4 * it + 0) * MD + lane];
                const float w1 = W1[(4 * it + 1) * MD + lane];
                const float w2 = W1[(4 * it + 2) * MD + lane];
                const float w3 = W1[(4 * it + 3) * MD + lane];
                #pragma unroll
                for (int r = 0; r < 8; r++) {
                    const float4 m = smc4[(grp + 2 * r) * (MN / 4) + it];
                    float t = fmaf(m.x, w0, m_a[r]);
                    t = fmaf(m.y, w1, t);
                    t = fmaf(m.z, w2, t);
                    m_a[r] = fmaf(m.w, w3, t);
                }
            }

            // (c) consume landed gather values
            g_acc0.x += (v0a.x + v0b.x) + (v0c.x + v0d.x);
            g_acc0.y += (v0a.y + v0b.y) + (v0c.y + v0d.y);
            g_acc0.z += (v0a.z + v0b.z) + (v0c.z + v0d.z);
            g_acc0.w += (v0a.w + v0b.w) + (v0c.w + v0d.w);
            g_acc1.x += (v1a.x + v1b.x) + (v1c.x + v1d.x);
            g_acc1.y += (v1a.y + v1b.y) + (v1c.y + v1d.y);
            g_acc1.z += (v1a.z + v1b.z) + (v1c.z + v1d.z);
            g_acc1.w += (v1a.w + v1b.w) + (v1c.w + v1d.w);
        }

        // pred gather (short) + finalize s_sem
        const float se = 0.5f / EPER, sp = 0.5f / PPER;
        g_acc0.x *= se; g_acc0.y *= se; g_acc0.z *= se; g_acc0.w *= se;
        g_acc1.x *= se; g_acc1.y *= se; g_acc1.z *= se; g_acc1.w *= se;

        const float4* ptab4 = (const float4*)ptab;
        const int4* pdx0 = (const int4*)(s_pidx + (r0 + 0) * PPER);
        const int4* pdx1 = (const int4*)(s_pidx + (r0 + 1) * PPER);
        #pragma unroll
        for (int e4 = 0; e4 < PPER / 4; e4++) {
            const int4 i0 = pdx0[e4];
            const int4 i1 = pdx1[e4];
            const float4 v0a = ptab4[(size_t)i0.x * 32 + wlane];
            const float4 v0b = ptab4[(size_t)i0.y * 32 + wlane];
            const float4 v0c = ptab4[(size_t)i0.z * 32 + wlane];
            const float4 v0d = ptab4[(size_t)i0.w * 32 + wlane];
            const float4 v1a = ptab4[(size_t)i1.x * 32 + wlane];
            const float4 v1b = ptab4[(size_t)i1.y * 32 + wlane];
            const float4 v1c = ptab4[(size_t)i1.z * 32 + wlane];
            const float4 v1d = ptab4[(size_t)i1.w * 32 + wlane];
            g_acc0.x = fmaf((v0a.x + v0b.x) + (v0c.x + v0d.x), sp, g_acc0.x);
            g_acc0.y = fmaf((v0a.y + v0b.y) + (v0c.y + v0d.y), sp, g_acc0.y);
            g_acc0.z = fmaf((v0a.z + v0b.z) + (v0c.z + v0d.z), sp, g_acc0.z);
            g_acc0.w = fmaf((v0a.w + v0b.w) + (v0c.w + v0d.w), sp, g_acc0.w);
            g_acc1.x = fmaf((v1a.x + v1b.x) + (v1c.x + v1d.x), sp, g_acc1.x);
            g_acc1.y = fmaf((v1a.y + v1b.y) + (v1c.y + v1d.y), sp, g_acc1.y);
            g_acc1.z = fmaf((v1a.z + v1b.z) + (v1c.z + v1d.z), sp, g_acc1.z);
            g_acc1.w = fmaf((v1a.w + v1b.w) + (v1c.w + v1d.w), sp, g_acc1.w);
        }
        ((float4*)(s_sem + (r0 + 0) * D_SZ))[wlane] = g_acc0;
        ((float4*)(s_sem + (r0 + 1) * D_SZ))[wlane] = g_acc1;

        // stage-2 epilogue: relu store
        #pragma unroll
        for (int r = 0; r < 8; r++)
            s_h1[(grp + 2 * r) * MD + lane] = fmaxf(m_a[r], 0.f);
    }
    __syncthreads();

    // ---- stage 3: m2 = relu(h1 @ W2 + b2); m2 aliases idx/mc region ----
    {
        float a[8];
        const float bb = b2[lane];
        #pragma unroll
        for (int r = 0; r < 8; r++) a[r] = bb;
        const float4* sh14 = (const float4*)s_h1;
        #pragma unroll 4
        for (int i4 = 0; i4 < MD / 4; i4++) {
            const float w0 = W2[(4 * i4 + 0) * MD + lane];
            const float w1 = W2[(4 * i4 + 1) * MD + lane];
            const float w2 = W2[(4 * i4 + 2) * MD + lane];
            const float w3 = W2[(4 * i4 + 3) * MD + lane];
            #pragma unroll
            for (int r = 0; r < 8; r++) {
                const float4 h = sh14[(grp + 2 * r) * (MD / 4) + i4];
                float t = fmaf(h.x, w0, a[r]);
                t = fmaf(h.y, w1, t);
                t = fmaf(h.z, w2, t);
                a[r] = fmaf(h.w, w3, t);
            }
        }
        __syncthreads();   // all readers of aliased region and s_h1 done
        #pragma unroll
        for (int r = 0; r < 8; r++)
            s_m2[(grp + 2 * r) * MD + lane] = fmaxf(a[r], 0.f);
    }
    __syncthreads();

    // ---- stage 4: out = relu(concat(sem, m2) @ Wf + bf), k-split (R8) ----
    {
        const int tx = tid & 63;
        const int ty = (tid >> 6) & 1;
        const int tz = tid >> 7;

        float acc[8][4];
        #pragma unroll
        for (int r = 0; r < 8; r++)
            #pragma unroll
            for (int c = 0; c < 4; c++) acc[r][c] = 0.f;

        const float4* act4 = tz ? (const float4*)s_m2 : (const float4*)s_sem;
        const float*  WfH  = Wf + (size_t)(tz * D_SZ) * OUTD;

        #pragma unroll 2
        for (int k4 = 0; k4 < D_SZ / 4; k4++) {
            const float4 w0 = ((const float4*)(WfH + (size_t)(4 * k4 + 0) * OUTD))[tx];
            const float4 w1 = ((const float4*)(WfH + (size_t)(4 * k4 + 1) * OUTD))[tx];
            const float4 w2 = ((const float4*)(WfH + (size_t)(4 * k4 + 2) * OUTD))[tx];
            const float4 w3 = ((const float4*)(WfH + (size_t)(4 * k4 + 3) * OUTD))[tx];
            #pragma unroll
            for (int r = 0; r < 8; r++) {
                const float4 a = act4[(8 * ty + r) * (D_SZ / 4) + k4];
                acc[r][0] = fmaf(a.x, w0.x, acc[r][0]);
                acc[r][1] = fmaf(a.x, w0.y, acc[r][1]);
                acc[r][2] = fmaf(a.x, w0.z, acc[r][2]);
                acc[r][3] = fmaf(a.x, w0.w, acc[r][3]);
                acc[r][0] = fmaf(a.y, w1.x, acc[r][0]);
                acc[r][1] = fmaf(a.y, w1.y, acc[r][1]);
                acc[r][2] = fmaf(a.y, w1.z, acc[r][2]);
                acc[r][3] = fmaf(a.y, w1.w, acc[r][3]);
                acc[r][0] = fmaf(a.z, w2.x, acc[r][0]);
                acc[r][1] = fmaf(a.z, w2.y, acc[r][1]);
                acc[r][2] = fmaf(a.z, w2.z, acc[r][2]);
                acc[r][3] = fmaf(a.z, w2.w, acc[r][3]);
                acc[r][0] = fmaf(a.w, w3.x, acc[r][0]);
                acc[r][1] = fmaf(a.w, w3.y, acc[r][1]);
                acc[r][2] = fmaf(a.w, w3.z, acc[r][2]);
                acc[r][3] = fmaf(a.w, w3.w, acc[r][3]);
            }
        }

        if (tz) {
            #pragma unroll
            for (int r = 0; r < 8; r++)
                s_part[(8 * ty + r) * 64 + tx] =
                    make_float4(acc[r][0], acc[r][1], acc[r][2], acc[r][3]);
        }
        __syncthreads();

        if (!tz) {
            const float4 bfv = ((const float4*)bf)[tx];
            #pragma unroll
            for (int r = 0; r < 8; r++) {
                const float4 p = s_part[(8 * ty + r) * 64 + tx];
                float4 o;
                o.x = fmaxf(acc[r][0] + p.x + bfv.x, 0.f);
                o.y = fmaxf(acc[r][1] + p.y + bfv.y, 0.f);
                o.z = fmaxf(acc[r][2] + p.z + bfv.z, 0.f);
                o.w = fmaxf(acc[r][3] + p.w + bfv.w, 0.f);
                ((float4*)(out + (size_t)(rowBase + 8 * ty + r) * OUTD))[tx] = o;
            }
        }
    }
}

extern "C" void kernel_launch(void* const* d_in, const int* in_sizes, int n_in,
                              void* d_out, int out_size)
{
    const int*   eidx = (const int*)d_in[0];
    const int*   pidx = (const int*)d_in[1];
    const float* mc   = (const float*)d_in[2];
    const float* etab = (const float*)d_in[3];
    const float* ptab = (const float*)d_in[4];
    const float* W1   = (const float*)d_in[5];
    const float* b1   = (const float*)d_in[6];
    const float* W2   = (const float*)d_in[7];
    const float* b2   = (const float*)d_in[8];
    const float* Wf   = (const float*)d_in[9];
    const float* bf   = (const float*)d_in[10];
    float* out = (float*)d_out;

    cudaFuncSetAttribute(subgraph_fused_kernel,
                         cudaFuncAttributeMaxDynamicSharedMemorySize, SMEM_BYTES);

    subgraph_fused_kernel<<<B_SZ / TM, NTHR, SMEM_BYTES>>>(
        eidx, pidx, mc, etab, ptab, W1, b1, W2, b2, Wf, bf, out);
}